// round 3
// baseline (speedup 1.0000x reference)
#include <cuda_runtime.h>
#include <cuda_bf16.h>
#include <math.h>

typedef unsigned long long ull;

#define SA 36          // padded k-stride (floats) for GEMM shared tiles
#define HSTR 260       // padded row stride (floats) for recurrence shared state
#define KB_SMEM ((12 + 64) * HSTR * 4)

// ------------------------- device scratch (zero-initialized) ----------------
__device__ float g_GI[2u * 128u * 768u * 64u];   // [dir][w][gaterow768][s]
__device__ float g_WENC[8192u * 512u];           // [(s*128+w)][dir*256+u]
__device__ float g_H[2 * 2 * 64 * 256];          // [pingpong][dir][s][u]
__device__ float g_SSUMP[2][64 * 512];           // partial sent_summ [whalf][s][col]
__device__ float g_SGI[3072 * 64];               // sentence GRU gates [row][s]
__device__ float g_SENT[64 * 1024];              // sentenc [s][2HS]
__device__ float g_DOC[1024];                    // doc vector
__device__ unsigned g_arrive;                    // grid barrier state
__device__ unsigned g_gen;

// ------------------------- helpers ------------------------------------------
__device__ __forceinline__ void fma2(ull& d, ull a, ull b) {
    asm("fma.rn.f32x2 %0, %1, %2, %0;" : "+l"(d) : "l"(a), "l"(b));
}
__device__ __forceinline__ float hsum2(ull v) {
    float lo, hi;
    asm("mov.b64 {%0,%1}, %2;" : "=f"(lo), "=f"(hi) : "l"(v));
    return lo + hi;
}
__device__ __forceinline__ float sigm(float x) { return 1.0f / (1.0f + expf(-x)); }

// Shared 128x64 GEMM tile inner product over a 32-wide K slab.
__device__ __forceinline__ void mm_tile(const float* __restrict__ Wsh,
                                        const float* __restrict__ Xsh,
                                        ull (&acc)[8][4], int tr, int tc) {
#pragma unroll
    for (int kk = 0; kk < 32; kk += 4) {
        ulonglong2 a[8], b[4];
#pragma unroll
        for (int i = 0; i < 8; i++)
            a[i] = *(const ulonglong2*)&Wsh[(tr + 16 * i) * SA + kk];
#pragma unroll
        for (int j = 0; j < 4; j++)
            b[j] = *(const ulonglong2*)&Xsh[(tc * 4 + j) * SA + kk];
#pragma unroll
        for (int i = 0; i < 8; i++)
#pragma unroll
            for (int j = 0; j < 4; j++) {
                fma2(acc[i][j], a[i].x, b[j].x);
                fma2(acc[i][j], a[i].y, b[j].y);
            }
    }
}

// ---------------------------------------------------------------------------
// Kernel A: GI[dir][w][row][s] = sum_d emb[doc[s][w]][d]*wWi[row][d] + biases
// grid (12 row-tiles of 128 over 1536 rows, 128 words), 256 threads.
// ---------------------------------------------------------------------------
__global__ __launch_bounds__(256) void kA(const int* __restrict__ doc,
                                          const float* __restrict__ emb,
                                          const float* __restrict__ wWi,
                                          const float* __restrict__ wbi,
                                          const float* __restrict__ wbh) {
    __shared__ float Wsh[128 * SA];
    __shared__ float Xsh[64 * SA];
    __shared__ int   sidx[64];
    const int t  = threadIdx.x;
    const int R0 = blockIdx.x * 128;
    const int w  = blockIdx.y;
    if (t < 64) sidx[t] = doc[t * 128 + w];

    ull acc[8][4];
#pragma unroll
    for (int i = 0; i < 8; i++)
#pragma unroll
        for (int j = 0; j < 4; j++) acc[i][j] = 0ull;
    const int tr = t & 15, tc = t >> 4;

    for (int k0 = 0; k0 < 256; k0 += 32) {
        __syncthreads();
        for (int i = t; i < 1024; i += 256) {           // 128 rows x 32 k
            int r = i >> 3, kq = i & 7;
            *(float4*)&Wsh[r * SA + kq * 4] =
                *(const float4*)&wWi[(size_t)(R0 + r) * 256 + k0 + kq * 4];
        }
        for (int i = t; i < 512; i += 256) {            // 64 s x 32 d (gather)
            int s = i >> 3, kq = i & 7;
            *(float4*)&Xsh[s * SA + kq * 4] =
                *(const float4*)&emb[(size_t)sidx[s] * 256 + k0 + kq * 4];
        }
        __syncthreads();
        mm_tile(Wsh, Xsh, acc, tr, tc);
    }

#pragma unroll
    for (int i = 0; i < 8; i++) {
        int R   = R0 + tr + 16 * i;
        int dir = R / 768, rr = R % 768;
        float bias = wbi[R] + (rr < 512 ? wbh[R] : 0.0f);   // fold bh into r,z
        size_t base = ((size_t)(dir * 128 + w) * 768 + rr) * 64;
        float4 o;
        o.x = hsum2(acc[i][0]) + bias;
        o.y = hsum2(acc[i][1]) + bias;
        o.z = hsum2(acc[i][2]) + bias;
        o.w = hsum2(acc[i][3]) + bias;
        *(float4*)&g_GI[base + tc * 4] = o;
    }
}

// ---------------------------------------------------------------------------
// Kernel B: persistent word bi-GRU. 128 blocks (dir, 4-unit group), 256 thr.
// ---------------------------------------------------------------------------
__device__ __forceinline__ void grid_barrier() {
    __threadfence();
    __syncthreads();
    if (threadIdx.x == 0) {
        unsigned gen = *(volatile unsigned*)&g_gen;
        if (atomicAdd(&g_arrive, 1u) == 127u) {
            *(volatile unsigned*)&g_arrive = 0u;
            __threadfence();
            atomicAdd(&g_gen, 1u);
        } else {
            while (*(volatile unsigned*)&g_gen == gen) { __nanosleep(64); }
        }
        __threadfence();
    }
    __syncthreads();
}

__global__ __launch_bounds__(256, 1) void kB(const float* __restrict__ wWh,
                                             const float* __restrict__ wbh) {
    extern __shared__ float sh[];
    float* Wsh = sh;                 // 12 rows x HSTR
    float* Hsh = sh + 12 * HSTR;     // 64 s x HSTR

    const int t   = threadIdx.x;
    const int b   = blockIdx.x;
    const int dir = b >> 6;
    const int u0  = (b & 63) * 4;

    // resident weight rows: gates r,z,n for this block's 4 units
    for (int i = t; i < 12 * 256; i += 256) {
        int row = i >> 8, k = i & 255;
        int g = row >> 2, ui = row & 3;
        Wsh[row * HSTR + k] = wWh[(size_t)(dir * 768 + g * 256 + u0 + ui) * 256 + k];
    }

    const int s  = t >> 2;
    const int ui = t & 3;
    const int u  = u0 + ui;
    const float bhn = wbh[dir * 768 + 512 + u];
    const ulonglong2* wr = (const ulonglong2*)&Wsh[(0 + ui) * HSTR];
    const ulonglong2* wz = (const ulonglong2*)&Wsh[(4 + ui) * HSTR];
    const ulonglong2* wn = (const ulonglong2*)&Wsh[(8 + ui) * HSTR];

    float h = 0.0f;   // this thread's (s,u) state, carried in register
    __syncthreads();

    for (int w = 0; w < 128; w++) {
        size_t gib = (size_t)(dir * 128 + w) * 768 * 64;
        float gr = g_GI[gib + (size_t)u * 64 + s];
        float gz = g_GI[gib + (size_t)(256 + u) * 64 + s];
        float gn = g_GI[gib + (size_t)(512 + u) * 64 + s];

        // stage full per-direction state into shared
        if (w == 0) {
            float4 z4 = make_float4(0.f, 0.f, 0.f, 0.f);
            for (int i = t; i < 4096; i += 256) {
                int ss = i >> 6, kq = i & 63;
                *(float4*)&Hsh[ss * HSTR + kq * 4] = z4;
            }
        } else {
            const float4* Hg = (const float4*)(g_H + ((size_t)(w & 1) * 2 + dir) * 64 * 256);
            for (int i = t; i < 4096; i += 256) {
                int ss = i >> 6, kq = i & 63;
                *(float4*)&Hsh[ss * HSTR + kq * 4] = Hg[i];
            }
        }
        __syncthreads();

        ull ar = 0ull, az = 0ull, an = 0ull;
        const ulonglong2* hp = (const ulonglong2*)&Hsh[s * HSTR];
#pragma unroll 8
        for (int kk = 0; kk < 64; kk++) {
            ulonglong2 h2 = hp[kk];
            ulonglong2 r2 = wr[kk];
            ulonglong2 z2 = wz[kk];
            ulonglong2 n2 = wn[kk];
            fma2(ar, h2.x, r2.x); fma2(ar, h2.y, r2.y);
            fma2(az, h2.x, z2.x); fma2(az, h2.y, z2.y);
            fma2(an, h2.x, n2.x); fma2(an, h2.y, n2.y);
        }
        float r = sigm(gr + hsum2(ar));                 // bi_r+bh_r folded in gr
        float z = sigm(gz + hsum2(az));
        float n = tanhf(gn + r * (hsum2(an) + bhn));
        h = (1.0f - z) * n + z * h;

        g_H[(((size_t)((w + 1) & 1) * 2 + dir) * 64 + s) * 256 + u] = h;
        g_WENC[(size_t)(s * 128 + w) * 512 + dir * 256 + u] = h;
        grid_barrier();
    }
}

// ---------------------------------------------------------------------------
// Kernel C: partial sent_summ[wh][s][col] = sum_{w in half} tanh(wenc@waW^T+b)
// grid (4 col-tiles, 2 word-halves, 64 sentences), 256 threads.
// ---------------------------------------------------------------------------
__global__ __launch_bounds__(256) void kC(const float* __restrict__ waW,
                                          const float* __restrict__ wab) {
    __shared__ float Wsh[128 * SA];
    __shared__ float Xsh[64 * SA];
    __shared__ float sred[128 * 16];
    const int t  = threadIdx.x;
    const int ct = blockIdx.x, wh = blockIdx.y, s = blockIdx.z;
    const int R0 = ct * 128;

    ull acc[8][4];
#pragma unroll
    for (int i = 0; i < 8; i++)
#pragma unroll
        for (int j = 0; j < 4; j++) acc[i][j] = 0ull;
    const int tr = t & 15, tc = t >> 4;

    for (int k0 = 0; k0 < 512; k0 += 32) {
        __syncthreads();
        for (int i = t; i < 1024; i += 256) {
            int r = i >> 3, kq = i & 7;
            *(float4*)&Wsh[r * SA + kq * 4] =
                *(const float4*)&waW[(size_t)(R0 + r) * 512 + k0 + kq * 4];
        }
        for (int i = t; i < 512; i += 256) {
            int ws = i >> 3, kq = i & 7;
            *(float4*)&Xsh[ws * SA + kq * 4] =
                *(const float4*)&g_WENC[(size_t)(s * 128 + wh * 64 + ws) * 512 + k0 + kq * 4];
        }
        __syncthreads();
        mm_tile(Wsh, Xsh, acc, tr, tc);
    }

#pragma unroll
    for (int i = 0; i < 8; i++) {
        float bias = wab[R0 + tr + 16 * i];
        float v = 0.0f;
#pragma unroll
        for (int j = 0; j < 4; j++) v += tanhf(hsum2(acc[i][j]) + bias);
        sred[(tr + 16 * i) * 16 + tc] = v;
    }
    __syncthreads();
    if (t < 128) {
        float v = 0.0f;
#pragma unroll
        for (int c = 0; c < 16; c++) v += sred[t * 16 + c];
        g_SSUMP[wh][s * 512 + R0 + t] = v;
    }
}

// ---------------------------------------------------------------------------
// Kernel D: sentence GRU input gates: g_SGI[row3072][s] = sent_summ@sWi^T+bias
// grid 24 blocks (128-row tiles), 256 threads. K=512.
// ---------------------------------------------------------------------------
__global__ __launch_bounds__(256) void kD(const float* __restrict__ sWi,
                                          const float* __restrict__ sbi,
                                          const float* __restrict__ sbh) {
    __shared__ float Wsh[128 * SA];
    __shared__ float Xsh[64 * SA];
    const int t  = threadIdx.x;
    const int R0 = blockIdx.x * 128;

    ull acc[8][4];
#pragma unroll
    for (int i = 0; i < 8; i++)
#pragma unroll
        for (int j = 0; j < 4; j++) acc[i][j] = 0ull;
    const int tr = t & 15, tc = t >> 4;

    for (int k0 = 0; k0 < 512; k0 += 32) {
        __syncthreads();
        for (int i = t; i < 1024; i += 256) {
            int r = i >> 3, kq = i & 7;
            *(float4*)&Wsh[r * SA + kq * 4] =
                *(const float4*)&sWi[(size_t)(R0 + r) * 512 + k0 + kq * 4];
        }
        for (int i = t; i < 512; i += 256) {
            int ss = i >> 3, kq = i & 7;
            float4 a = *(const float4*)&g_SSUMP[0][ss * 512 + k0 + kq * 4];
            float4 b = *(const float4*)&g_SSUMP[1][ss * 512 + k0 + kq * 4];
            *(float4*)&Xsh[ss * SA + kq * 4] =
                make_float4(a.x + b.x, a.y + b.y, a.z + b.z, a.w + b.w);
        }
        __syncthreads();
        mm_tile(Wsh, Xsh, acc, tr, tc);
    }

#pragma unroll
    for (int i = 0; i < 8; i++) {
        int R  = R0 + tr + 16 * i;
        int rr = R % 1536;
        float bias = sbi[R] + (rr < 1024 ? sbh[R] : 0.0f);
#pragma unroll
        for (int j = 0; j < 4; j++)
            g_SGI[R * 64 + tc * 4 + j] = hsum2(acc[i][j]) + bias;
    }
}

// ---------------------------------------------------------------------------
// Kernel E: sentence GRU combine (h0 = 0) -> sentenc[s][dir*512+u]
// ---------------------------------------------------------------------------
__global__ __launch_bounds__(512) void kE(const float* __restrict__ sbh) {
    int idx = blockIdx.x * 512 + threadIdx.x;       // 65536
    int u = idx & 511, s = (idx >> 9) & 63, dir = idx >> 15;
    float gr = g_SGI[(dir * 1536 + u) * 64 + s];
    float gz = g_SGI[(dir * 1536 + 512 + u) * 64 + s];
    float gn = g_SGI[(dir * 1536 + 1024 + u) * 64 + s];
    float bhn = sbh[dir * 1536 + 1024 + u];
    float r = sigm(gr);
    float z = sigm(gz);
    float n = tanhf(gn + r * bhn);
    g_SENT[s * 1024 + dir * 512 + u] = (1.0f - z) * n;
}

// ---------------------------------------------------------------------------
// Kernel F: doc[col] = sum_s tanh(sentenc @ saW^T + sab). grid 8, K=1024.
// ---------------------------------------------------------------------------
__global__ __launch_bounds__(256) void kF(const float* __restrict__ saW,
                                          const float* __restrict__ sab) {
    __shared__ float Wsh[128 * SA];
    __shared__ float Xsh[64 * SA];
    __shared__ float sred[128 * 16];
    const int t  = threadIdx.x;
    const int R0 = blockIdx.x * 128;

    ull acc[8][4];
#pragma unroll
    for (int i = 0; i < 8; i++)
#pragma unroll
        for (int j = 0; j < 4; j++) acc[i][j] = 0ull;
    const int tr = t & 15, tc = t >> 4;

    for (int k0 = 0; k0 < 1024; k0 += 32) {
        __syncthreads();
        for (int i = t; i < 1024; i += 256) {
            int r = i >> 3, kq = i & 7;
            *(float4*)&Wsh[r * SA + kq * 4] =
                *(const float4*)&saW[(size_t)(R0 + r) * 1024 + k0 + kq * 4];
        }
        for (int i = t; i < 512; i += 256) {
            int ss = i >> 3, kq = i & 7;
            *(float4*)&Xsh[ss * SA + kq * 4] =
                *(const float4*)&g_SENT[ss * 1024 + k0 + kq * 4];
        }
        __syncthreads();
        mm_tile(Wsh, Xsh, acc, tr, tc);
    }

#pragma unroll
    for (int i = 0; i < 8; i++) {
        float bias = sab[R0 + tr + 16 * i];
        float v = 0.0f;
#pragma unroll
        for (int j = 0; j < 4; j++) v += tanhf(hsum2(acc[i][j]) + bias);
        sred[(tr + 16 * i) * 16 + tc] = v;
    }
    __syncthreads();
    if (t < 128) {
        float v = 0.0f;
#pragma unroll
        for (int c = 0; c < 16; c++) v += sred[t * 16 + c];
        g_DOC[R0 + t] = v;
    }
}

// ---------------------------------------------------------------------------
// Kernel G: blocks 0..32 write the all-ones attention weights; block 33
// computes logits = doc @ doW^T + dob and writes log_softmax.
// ---------------------------------------------------------------------------
__global__ __launch_bounds__(256) void kG(const float* __restrict__ doW,
                                          const float* __restrict__ dob,
                                          float* __restrict__ out, int out_size) {
    const int t = threadIdx.x;
    if (blockIdx.x < 33) {
        int idx = blockIdx.x * 256 + t;
        if (idx < out_size - 13) out[idx] = 1.0f;
        return;
    }
    __shared__ float red[256];
    __shared__ float lg[13];
    for (int c = 0; c < 13; c++) {
        float v = 0.0f;
        for (int k = t; k < 1024; k += 256) v += g_DOC[k] * doW[c * 1024 + k];
        red[t] = v;
        __syncthreads();
        for (int s2 = 128; s2 > 0; s2 >>= 1) {
            if (t < s2) red[t] += red[t + s2];
            __syncthreads();
        }
        if (t == 0) lg[c] = red[0] + dob[c];
        __syncthreads();
    }
    if (t == 0) {
        float m = lg[0];
        for (int c = 1; c < 13; c++) m = fmaxf(m, lg[c]);
        float sum = 0.0f;
        for (int c = 0; c < 13; c++) sum += expf(lg[c] - m);
        float l = logf(sum);
        int base = out_size - 13;
        for (int c = 0; c < 13; c++) out[base + c] = lg[c] - m - l;
    }
}

// ---------------------------------------------------------------------------
extern "C" void kernel_launch(void* const* d_in, const int* in_sizes, int n_in,
                              void* d_out, int out_size) {
    const int*   doc = (const int*)d_in[0];
    const float* emb = (const float*)d_in[1];
    const float* wWi = (const float*)d_in[2];
    const float* wWh = (const float*)d_in[3];
    const float* wbi = (const float*)d_in[4];
    const float* wbh = (const float*)d_in[5];
    const float* sWi = (const float*)d_in[6];
    const float* sbi = (const float*)d_in[8];
    const float* sbh = (const float*)d_in[9];
    const float* waW = (const float*)d_in[10];
    const float* wab = (const float*)d_in[11];
    const float* saW = (const float*)d_in[13];
    const float* sab = (const float*)d_in[14];
    const float* doW = (const float*)d_in[16];
    const float* dob = (const float*)d_in[17];
    float* out = (float*)d_out;

    cudaFuncSetAttribute(kB, cudaFuncAttributeMaxDynamicSharedMemorySize, KB_SMEM);

    kA<<<dim3(12, 128), 256>>>(doc, emb, wWi, wbi, wbh);
    kB<<<128, 256, KB_SMEM>>>(wWh, wbh);
    kC<<<dim3(4, 2, 64), 256>>>(waW, wab);
    kD<<<24, 256>>>(sWi, sbi, sbh);
    kE<<<128, 512>>>(sbh);
    kF<<<8, 256>>>(saW, sab);
    kG<<<34, 256>>>(doW, dob, out, out_size);
}